// round 3
// baseline (speedup 1.0000x reference)
#include <cuda_runtime.h>

// Problem constants
constexpr int CDIM  = 384;
constexpr int NHEAD = 12;
constexpr int DHEAD = 32;
constexpr int NB    = 16;
constexpr int NN    = 1024;            // 32*32 tokens
constexpr int MT    = NB * NN;         // 16384 rows
constexpr float QK_SCALE = 0.17677669529663687f; // 32^-0.5

// Scratch (static device globals; no runtime allocation)
__device__ float g_q[(size_t)NB * NHEAD * NN * DHEAD];
__device__ float g_k[(size_t)NB * NHEAD * NN * DHEAD];
__device__ float g_v[(size_t)NB * NHEAD * NN * DHEAD];
__device__ float g_ao[(size_t)MT * CDIM];   // attention output [m][c]

// ---------------------------------------------------------------------------
// Kernel 1: QKV GEMM.  C[m][o] = sum_c x[b,c,n] * w[o,c],  m=b*NN+n.
// Tile 128x128, K-step 8, 256 threads, 8x8 per thread.
// Epilogue scatters into g_q/g_k/g_v with [b,h,n,d] layout.
// (Resubmission of R1 — prior round failed on container infra, no signal.)
// ---------------------------------------------------------------------------
__global__ __launch_bounds__(256) void qkv_gemm(const float* __restrict__ x,
                                                const float* __restrict__ w) {
    __shared__ float As[8][128];   // [k][m], m-fastest store: conflict-free
    __shared__ float Bs[8][136];   // [k][o], padded, 16B-aligned rows

    const int m0 = blockIdx.x * 128;
    const int o0 = blockIdx.y * 128;
    const int b  = m0 / NN;
    const int n0 = m0 % NN;
    const int t  = threadIdx.x;

    const float* xb = x + (size_t)b * CDIM * NN + n0;

    float acc[8][8];
    #pragma unroll
    for (int i = 0; i < 8; i++)
        #pragma unroll
        for (int j = 0; j < 8; j++) acc[i][j] = 0.f;

    const int tr = (t >> 4) << 3;
    const int tc = (t & 15) << 3;

    for (int k0 = 0; k0 < CDIM; k0 += 8) {
        // A tile: i -> m=i&127 (fastest, coalesced over n), k=i>>7
        #pragma unroll
        for (int r = 0; r < 4; r++) {
            int i  = t + 256 * r;
            int mm = i & 127, kk = i >> 7;
            As[kk][mm] = xb[(size_t)(k0 + kk) * NN + mm];
        }
        // B tile: i -> k=i&7 (fastest, 32B runs), o=i>>3
        #pragma unroll
        for (int r = 0; r < 4; r++) {
            int i  = t + 256 * r;
            int kk = i & 7, oo = i >> 3;
            Bs[kk][oo] = w[(size_t)(o0 + oo) * CDIM + k0 + kk];
        }
        __syncthreads();
        #pragma unroll
        for (int kk = 0; kk < 8; kk++) {
            float4 a0 = *(const float4*)&As[kk][tr];
            float4 a1 = *(const float4*)&As[kk][tr + 4];
            float4 b0 = *(const float4*)&Bs[kk][tc];
            float4 b1 = *(const float4*)&Bs[kk][tc + 4];
            float a[8] = {a0.x, a0.y, a0.z, a0.w, a1.x, a1.y, a1.z, a1.w};
            float bb[8] = {b0.x, b0.y, b0.z, b0.w, b1.x, b1.y, b1.z, b1.w};
            #pragma unroll
            for (int i = 0; i < 8; i++)
                #pragma unroll
                for (int j = 0; j < 8; j++) acc[i][j] += a[i] * bb[j];
        }
        __syncthreads();
    }

    // Epilogue: scatter 8x8 into Q/K/V [b,h,n,d] (float4 groups never straddle
    // a 32-wide d-boundary because tc,j4 are multiples of 4 and 384%32==0).
    #pragma unroll
    for (int i = 0; i < 8; i++) {
        int n = (m0 + tr + i) & (NN - 1);
        #pragma unroll
        for (int j4 = 0; j4 < 8; j4 += 4) {
            int c     = o0 + tc + j4;
            int which = c / CDIM;
            int rem   = c % CDIM;
            int h     = rem >> 5;
            int d     = rem & 31;
            float* base = (which == 0) ? g_q : (which == 1) ? g_k : g_v;
            float* dst  = base + (((size_t)(b * NHEAD + h) * NN + n) * DHEAD + d);
            *(float4*)dst = make_float4(acc[i][j4], acc[i][j4 + 1],
                                        acc[i][j4 + 2], acc[i][j4 + 3]);
        }
    }
}

// ---------------------------------------------------------------------------
// Kernel 2: flash attention per (b,h).  One thread owns one query row.
// K/V tiles of 128 rows staged in smem; broadcast reads; online softmax with
// amortized rescale (running max rarely increases on random data).
// ---------------------------------------------------------------------------
__global__ __launch_bounds__(128) void attn_kernel() {
    __shared__ float4 Ks[128][8];
    __shared__ float4 Vs[128][8];

    const int bh = blockIdx.y;                       // b*NHEAD + h
    const int n  = blockIdx.x * 128 + threadIdx.x;   // query row

    const float* qp = g_q + ((size_t)bh * NN + n) * DHEAD;
    float q[32];
    #pragma unroll
    for (int i = 0; i < 32; i += 4) {
        float4 v4 = *(const float4*)(qp + i);
        q[i] = v4.x * QK_SCALE; q[i + 1] = v4.y * QK_SCALE;
        q[i + 2] = v4.z * QK_SCALE; q[i + 3] = v4.w * QK_SCALE;
    }

    float o[32];
    #pragma unroll
    for (int i = 0; i < 32; i++) o[i] = 0.f;
    float mx = -1e30f, l = 0.f;

    for (int m0 = 0; m0 < NN; m0 += 128) {
        const float4* kp = (const float4*)(g_k + ((size_t)bh * NN + m0) * DHEAD);
        const float4* vp = (const float4*)(g_v + ((size_t)bh * NN + m0) * DHEAD);
        __syncthreads();
        #pragma unroll
        for (int r = 0; r < 8; r++) {
            int idx = threadIdx.x + 128 * r;   // 1024 float4 per tile
            ((float4*)Ks)[idx] = kp[idx];
            ((float4*)Vs)[idx] = vp[idx];
        }
        __syncthreads();

        for (int j = 0; j < 128; j++) {
            float s = 0.f;
            #pragma unroll
            for (int kk = 0; kk < 8; kk++) {
                float4 kv = Ks[j][kk];
                s += q[kk * 4 + 0] * kv.x + q[kk * 4 + 1] * kv.y
                   + q[kk * 4 + 2] * kv.z + q[kk * 4 + 3] * kv.w;
            }
            if (s > mx) {                      // rare: ~ln(1024) times per row
                float corr = __expf(mx - s);
                l *= corr;
                #pragma unroll
                for (int d = 0; d < 32; d++) o[d] *= corr;
                mx = s;
            }
            float p = __expf(s - mx);
            l += p;
            #pragma unroll
            for (int kk = 0; kk < 8; kk++) {
                float4 vv = Vs[j][kk];
                o[kk * 4 + 0] += p * vv.x; o[kk * 4 + 1] += p * vv.y;
                o[kk * 4 + 2] += p * vv.z; o[kk * 4 + 3] += p * vv.w;
            }
        }
    }

    const float inv = 1.0f / l;
    const int b = bh / NHEAD, h = bh % NHEAD;
    float* op = g_ao + ((size_t)(b * NN) + n) * CDIM + h * DHEAD;
    #pragma unroll
    for (int i = 0; i < 32; i += 4)
        *(float4*)(op + i) = make_float4(o[i] * inv, o[i + 1] * inv,
                                         o[i + 2] * inv, o[i + 3] * inv);
}

// ---------------------------------------------------------------------------
// Kernel 3: projection GEMM + bias, transposed store to [b, c, n].
// out[b,c,n] = sum_k g_ao[m][k] * w[c][k] + bias[c],  m = b*NN+n.
// ---------------------------------------------------------------------------
__global__ __launch_bounds__(256) void proj_gemm(const float* __restrict__ w,
                                                 const float* __restrict__ bias,
                                                 float* __restrict__ out) {
    __shared__ float As[8][136];   // [k][m]
    __shared__ float Bs[8][136];   // [k][o]

    const int m0 = blockIdx.x * 128;
    const int o0 = blockIdx.y * 128;
    const int b  = m0 / NN;
    const int t  = threadIdx.x;

    float acc[8][8];
    #pragma unroll
    for (int i = 0; i < 8; i++)
        #pragma unroll
        for (int j = 0; j < 8; j++) acc[i][j] = 0.f;

    const int tr = (t >> 4) << 3;
    const int tc = (t & 15) << 3;

    for (int k0 = 0; k0 < CDIM; k0 += 8) {
        #pragma unroll
        for (int r = 0; r < 4; r++) {
            int i  = t + 256 * r;
            int kk = i & 7, mm = i >> 3;
            As[kk][mm] = g_ao[(size_t)(m0 + mm) * CDIM + k0 + kk];
        }
        #pragma unroll
        for (int r = 0; r < 4; r++) {
            int i  = t + 256 * r;
            int kk = i & 7, oo = i >> 3;
            Bs[kk][oo] = w[(size_t)(o0 + oo) * CDIM + k0 + kk];
        }
        __syncthreads();
        #pragma unroll
        for (int kk = 0; kk < 8; kk++) {
            float4 a0 = *(const float4*)&As[kk][tr];
            float4 a1 = *(const float4*)&As[kk][tr + 4];
            float4 b0 = *(const float4*)&Bs[kk][tc];
            float4 b1 = *(const float4*)&Bs[kk][tc + 4];
            float a[8] = {a0.x, a0.y, a0.z, a0.w, a1.x, a1.y, a1.z, a1.w};
            float bb[8] = {b0.x, b0.y, b0.z, b0.w, b1.x, b1.y, b1.z, b1.w};
            #pragma unroll
            for (int i = 0; i < 8; i++)
                #pragma unroll
                for (int j = 0; j < 8; j++) acc[i][j] += a[i] * bb[j];
        }
        __syncthreads();
    }

    // Transposed store out[b][c][n] + bias
    #pragma unroll
    for (int i = 0; i < 8; i++) {
        int n = (m0 + tr + i) & (NN - 1);
        #pragma unroll
        for (int j = 0; j < 8; j++) {
            int c = o0 + tc + j;
            out[((size_t)b * CDIM + c) * NN + n] = acc[i][j] + bias[c];
        }
    }
}

// ---------------------------------------------------------------------------
extern "C" void kernel_launch(void* const* d_in, const int* in_sizes, int n_in,
                              void* d_out, int out_size) {
    const float* x      = (const float*)d_in[0];   // [16,384,32,32]
    const float* qkv_w  = (const float*)d_in[1];   // [1152,384]
    const float* proj_w = (const float*)d_in[2];   // [384,384]
    const float* proj_b = (const float*)d_in[3];   // [384]
    float* out = (float*)d_out;                    // [16,384,32,32]

    qkv_gemm<<<dim3(MT / 128, (3 * CDIM) / 128), 256>>>(x, qkv_w);
    attn_kernel<<<dim3(NN / 128, NB * NHEAD), 128>>>();
    proj_gemm<<<dim3(MT / 128, CDIM / 128), 256>>>(proj_w, proj_b, out);
}

// round 6
// speedup vs baseline: 1.7707x; 1.7707x over previous
#include <cuda_runtime.h>
#include <cuda_bf16.h>
#include <cstdint>

// Problem constants
constexpr int CDIM  = 384;
constexpr int NHEAD = 12;
constexpr int DHEAD = 32;
constexpr int NB    = 16;
constexpr int NN    = 1024;            // 32*32 tokens
constexpr int MT    = NB * NN;         // 16384 rows
constexpr float QK_SCALE = 0.17677669529663687f; // 32^-0.5
constexpr float LOG2E    = 1.4426950408889634f;

// Scratch (static device globals; no runtime allocation)
__device__ float g_q[(size_t)NB * NHEAD * NN * DHEAD];
__device__ float g_k[(size_t)NB * NHEAD * NN * DHEAD];
__device__ float g_v[(size_t)NB * NHEAD * NN * DHEAD];
__device__ float g_ao[(size_t)MT * CDIM];   // attention output [m][c]

// ===========================================================================
// Helpers
// ===========================================================================
__device__ __forceinline__ float ex2f(float x) {
    float y; asm("ex2.approx.ftz.f32 %0, %1;" : "=f"(y) : "f"(x)); return y;
}
// Split (a,b) into bf16 hi pair and bf16 lo (residual) pair, packed b32.
__device__ __forceinline__ void split2(float a, float b, uint32_t& hi, uint32_t& lo) {
    __nv_bfloat16 ah = __float2bfloat16(a), bh = __float2bfloat16(b);
    float ar = a - __bfloat162float(ah), br = b - __bfloat162float(bh);
    __nv_bfloat162 H = __halves2bfloat162(ah, bh);
    __nv_bfloat162 L = __halves2bfloat162(__float2bfloat16(ar), __float2bfloat16(br));
    hi = *(uint32_t*)&H; lo = *(uint32_t*)&L;
}
__device__ __forceinline__ uint32_t smem_u32(const void* p) {
    uint32_t a;
    asm("{ .reg .u64 t; cvta.to.shared.u64 t, %1; cvt.u32.u64 %0, t; }"
        : "=r"(a) : "l"(p));
    return a;
}
#define LDMX2(r0, r1, addr) \
    asm volatile("ldmatrix.sync.aligned.m8n8.x2.shared.b16 {%0,%1}, [%2];" \
                 : "=r"(r0), "=r"(r1) : "r"(addr))
#define LDMX2T(r0, r1, addr) \
    asm volatile("ldmatrix.sync.aligned.m8n8.x2.trans.shared.b16 {%0,%1}, [%2];" \
                 : "=r"(r0), "=r"(r1) : "r"(addr))
__device__ __forceinline__ void mma_bf16(float* d, const uint32_t* a,
                                         uint32_t b0, uint32_t b1) {
    asm volatile(
        "mma.sync.aligned.m16n8k16.row.col.f32.bf16.bf16.f32 "
        "{%0,%1,%2,%3}, {%4,%5,%6,%7}, {%8,%9}, {%0,%1,%2,%3};"
        : "+f"(d[0]), "+f"(d[1]), "+f"(d[2]), "+f"(d[3])
        : "r"(a[0]), "r"(a[1]), "r"(a[2]), "r"(a[3]), "r"(b0), "r"(b1));
}

// ---------------------------------------------------------------------------
// Kernel 1: QKV GEMM (fp32 FMA, unchanged from verified baseline).
// ---------------------------------------------------------------------------
__global__ __launch_bounds__(256) void qkv_gemm(const float* __restrict__ x,
                                                const float* __restrict__ w) {
    __shared__ float As[8][128];
    __shared__ float Bs[8][136];

    const int m0 = blockIdx.x * 128;
    const int o0 = blockIdx.y * 128;
    const int b  = m0 / NN;
    const int n0 = m0 % NN;
    const int t  = threadIdx.x;

    const float* xb = x + (size_t)b * CDIM * NN + n0;

    float acc[8][8];
    #pragma unroll
    for (int i = 0; i < 8; i++)
        #pragma unroll
        for (int j = 0; j < 8; j++) acc[i][j] = 0.f;

    const int tr = (t >> 4) << 3;
    const int tc = (t & 15) << 3;

    for (int k0 = 0; k0 < CDIM; k0 += 8) {
        #pragma unroll
        for (int r = 0; r < 4; r++) {
            int i  = t + 256 * r;
            int mm = i & 127, kk = i >> 7;
            As[kk][mm] = xb[(size_t)(k0 + kk) * NN + mm];
        }
        #pragma unroll
        for (int r = 0; r < 4; r++) {
            int i  = t + 256 * r;
            int kk = i & 7, oo = i >> 3;
            Bs[kk][oo] = w[(size_t)(o0 + oo) * CDIM + k0 + kk];
        }
        __syncthreads();
        #pragma unroll
        for (int kk = 0; kk < 8; kk++) {
            float4 a0 = *(const float4*)&As[kk][tr];
            float4 a1 = *(const float4*)&As[kk][tr + 4];
            float4 b0 = *(const float4*)&Bs[kk][tc];
            float4 b1 = *(const float4*)&Bs[kk][tc + 4];
            float a[8] = {a0.x, a0.y, a0.z, a0.w, a1.x, a1.y, a1.z, a1.w};
            float bb[8] = {b0.x, b0.y, b0.z, b0.w, b1.x, b1.y, b1.z, b1.w};
            #pragma unroll
            for (int i = 0; i < 8; i++)
                #pragma unroll
                for (int j = 0; j < 8; j++) acc[i][j] += a[i] * bb[j];
        }
        __syncthreads();
    }

    #pragma unroll
    for (int i = 0; i < 8; i++) {
        int n = (m0 + tr + i) & (NN - 1);
        #pragma unroll
        for (int j4 = 0; j4 < 8; j4 += 4) {
            int c     = o0 + tc + j4;
            int which = c / CDIM;
            int rem   = c % CDIM;
            int h     = rem >> 5;
            int d     = rem & 31;
            float* base = (which == 0) ? g_q : (which == 1) ? g_k : g_v;
            float* dst  = base + (((size_t)(b * NHEAD + h) * NN + n) * DHEAD + d);
            *(float4*)dst = make_float4(acc[i][j4], acc[i][j4 + 1],
                                        acc[i][j4 + 2], acc[i][j4 + 3]);
        }
    }
}

// ---------------------------------------------------------------------------
// Kernel 2: flash attention on mma.sync bf16x3.
// CTA = (b,h) x 128 queries; 4 warps, each owns 32 query rows.
// 16 chunks of 64 keys. S and P stay in register fragments.
// ---------------------------------------------------------------------------
constexpr int ROWB = 80;   // smem row stride bytes (32 bf16 = 64B data + 16B pad)

__global__ __launch_bounds__(128) void attn_mma() {
    __shared__ __align__(16) char sk_h[64 * ROWB];
    __shared__ __align__(16) char sk_l[64 * ROWB];
    __shared__ __align__(16) char sv_h[64 * ROWB];
    __shared__ __align__(16) char sv_l[64 * ROWB];

    const int tid = threadIdx.x;
    const int w   = tid >> 5;
    const int l   = tid & 31;
    const int g   = l >> 2;      // row-in-8 group
    const int t4  = l & 3;       // col pair index
    const int bh  = blockIdx.y;
    const int n0  = blockIdx.x * 128;

    const uint32_t skh = smem_u32(sk_h), skl = smem_u32(sk_l);
    const uint32_t svh = smem_u32(sv_h), svl = smem_u32(sv_l);

    // ---- Q fragments (scale*log2e folded), bf16 hi/lo, loaded once ----
    uint32_t qh[2][2][4], ql[2][2][4];
    {
        const float qs = QK_SCALE * LOG2E;
        const float* qb = g_q + ((size_t)bh * NN + n0 + w * 32) * DHEAD;
        #pragma unroll
        for (int mt = 0; mt < 2; mt++)
            #pragma unroll
            for (int ks = 0; ks < 2; ks++) {
                int rA = mt * 16 + g, rB = rA + 8, kk = ks * 16 + t4 * 2;
                float2 v0 = *(const float2*)(qb + rA * DHEAD + kk);
                float2 v1 = *(const float2*)(qb + rB * DHEAD + kk);
                float2 v2 = *(const float2*)(qb + rA * DHEAD + kk + 8);
                float2 v3 = *(const float2*)(qb + rB * DHEAD + kk + 8);
                split2(v0.x * qs, v0.y * qs, qh[mt][ks][0], ql[mt][ks][0]);
                split2(v1.x * qs, v1.y * qs, qh[mt][ks][1], ql[mt][ks][1]);
                split2(v2.x * qs, v2.y * qs, qh[mt][ks][2], ql[mt][ks][2]);
                split2(v3.x * qs, v3.y * qs, qh[mt][ks][3], ql[mt][ks][3]);
            }
    }

    float of[2][4][4];
    #pragma unroll
    for (int mt = 0; mt < 2; mt++)
        #pragma unroll
        for (int nt = 0; nt < 4; nt++)
            #pragma unroll
            for (int e = 0; e < 4; e++) of[mt][nt][e] = 0.f;

    float m0A[2] = {0.f, 0.f}, m0B[2] = {0.f, 0.f};
    float lA[2] = {0.f, 0.f}, lB[2] = {0.f, 0.f};

    const int   krow = tid >> 1;
    const int   kd0  = (tid & 1) * 16;
    const float* kpb = g_k + (size_t)bh * NN * DHEAD;
    const float* vpb = g_v + (size_t)bh * NN * DHEAD;

    for (int it = 0; it < 16; it++) {
        __syncthreads();   // previous chunk's smem reads done
        // ---- load + bf16-split K/V chunk into smem ----
        {
            const float* kp = kpb + (size_t)(it * 64 + krow) * DHEAD + kd0;
            const float* vp = vpb + (size_t)(it * 64 + krow) * DHEAD + kd0;
            uint32_t kh[8], kl2[8], vh[8], vl2[8];
            #pragma unroll
            for (int i = 0; i < 16; i += 2) {
                float2 kf = *(const float2*)(kp + i);
                float2 vf = *(const float2*)(vp + i);
                split2(kf.x, kf.y, kh[i / 2], kl2[i / 2]);
                split2(vf.x, vf.y, vh[i / 2], vl2[i / 2]);
            }
            const int off = krow * ROWB + kd0 * 2;
            *(uint4*)(sk_h + off)      = make_uint4(kh[0], kh[1], kh[2], kh[3]);
            *(uint4*)(sk_h + off + 16) = make_uint4(kh[4], kh[5], kh[6], kh[7]);
            *(uint4*)(sk_l + off)      = make_uint4(kl2[0], kl2[1], kl2[2], kl2[3]);
            *(uint4*)(sk_l + off + 16) = make_uint4(kl2[4], kl2[5], kl2[6], kl2[7]);
            *(uint4*)(sv_h + off)      = make_uint4(vh[0], vh[1], vh[2], vh[3]);
            *(uint4*)(sv_h + off + 16) = make_uint4(vh[4], vh[5], vh[6], vh[7]);
            *(uint4*)(sv_l + off)      = make_uint4(vl2[0], vl2[1], vl2[2], vl2[3]);
            *(uint4*)(sv_l + off + 16) = make_uint4(vl2[4], vl2[5], vl2[6], vl2[7]);
        }
        __syncthreads();

        // ---- S = Q.K^T  (bf16x3), fragments fresh per chunk ----
        float sf[2][8][4];
        #pragma unroll
        for (int mt = 0; mt < 2; mt++)
            #pragma unroll
            for (int nt = 0; nt < 8; nt++)
                #pragma unroll
                for (int e = 0; e < 4; e++) sf[mt][nt][e] = 0.f;

        const int lane = l & 15;
        #pragma unroll
        for (int nt = 0; nt < 8; nt++) {
            #pragma unroll
            for (int ks = 0; ks < 2; ks++) {
                uint32_t aoff = (uint32_t)((nt * 8 + (lane & 7)) * ROWB
                                           + (ks * 16 + (lane >> 3) * 8) * 2);
                uint32_t bh0, bh1, bl0, bl1;
                LDMX2(bh0, bh1, skh + aoff);
                LDMX2(bl0, bl1, skl + aoff);
                #pragma unroll
                for (int mt = 0; mt < 2; mt++) {
                    mma_bf16(sf[mt][nt], qh[mt][ks], bh0, bh1);
                    mma_bf16(sf[mt][nt], qh[mt][ks], bl0, bl1);
                    mma_bf16(sf[mt][nt], ql[mt][ks], bh0, bh1);
                }
            }
        }

        // ---- softmax (log2 domain, fixed m0 from chunk 0) ----
        if (it == 0) {
            #pragma unroll
            for (int mt = 0; mt < 2; mt++) {
                float mA = -1e30f, mB = -1e30f;
                #pragma unroll
                for (int nt = 0; nt < 8; nt++) {
                    mA = fmaxf(mA, fmaxf(sf[mt][nt][0], sf[mt][nt][1]));
                    mB = fmaxf(mB, fmaxf(sf[mt][nt][2], sf[mt][nt][3]));
                }
                mA = fmaxf(mA, __shfl_xor_sync(0xffffffffu, mA, 1));
                mA = fmaxf(mA, __shfl_xor_sync(0xffffffffu, mA, 2));
                mB = fmaxf(mB, __shfl_xor_sync(0xffffffffu, mB, 1));
                mB = fmaxf(mB, __shfl_xor_sync(0xffffffffu, mB, 2));
                m0A[mt] = mA; m0B[mt] = mB;
            }
        }

        uint32_t ph[2][8][2], pl[2][8][2];
        #pragma unroll
        for (int mt = 0; mt < 2; mt++) {
            #pragma unroll
            for (int nt = 0; nt < 8; nt++) {
                float p0 = ex2f(sf[mt][nt][0] - m0A[mt]);
                float p1 = ex2f(sf[mt][nt][1] - m0A[mt]);
                float p2 = ex2f(sf[mt][nt][2] - m0B[mt]);
                float p3 = ex2f(sf[mt][nt][3] - m0B[mt]);
                lA[mt] += p0 + p1;
                lB[mt] += p2 + p3;
                split2(p0, p1, ph[mt][nt][0], pl[mt][nt][0]);
                split2(p2, p3, ph[mt][nt][1], pl[mt][nt][1]);
            }
        }

        // ---- O += P.V  (bf16x3) ----
        #pragma unroll
        for (int s = 0; s < 4; s++) {
            #pragma unroll
            for (int nt = 0; nt < 4; nt++) {
                uint32_t voff = (uint32_t)((s * 16 + lane) * ROWB + nt * 16);
                uint32_t vh0, vh1, vl0, vl1;
                LDMX2T(vh0, vh1, svh + voff);
                LDMX2T(vl0, vl1, svl + voff);
                #pragma unroll
                for (int mt = 0; mt < 2; mt++) {
                    uint32_t ah[4] = {ph[mt][2 * s][0], ph[mt][2 * s][1],
                                      ph[mt][2 * s + 1][0], ph[mt][2 * s + 1][1]};
                    uint32_t al[4] = {pl[mt][2 * s][0], pl[mt][2 * s][1],
                                      pl[mt][2 * s + 1][0], pl[mt][2 * s + 1][1]};
                    mma_bf16(of[mt][nt], ah, vh0, vh1);
                    mma_bf16(of[mt][nt], ah, vl0, vl1);
                    mma_bf16(of[mt][nt], al, vh0, vh1);
                }
            }
        }
    }

    // ---- normalize + write g_ao[m][c] ----
    const int bb = bh / NHEAD, hh = bh % NHEAD;
    #pragma unroll
    for (int mt = 0; mt < 2; mt++) {
        float a = lA[mt], b2 = lB[mt];
        a  += __shfl_xor_sync(0xffffffffu, a, 1);
        a  += __shfl_xor_sync(0xffffffffu, a, 2);
        b2 += __shfl_xor_sync(0xffffffffu, b2, 1);
        b2 += __shfl_xor_sync(0xffffffffu, b2, 2);
        const float ia = 1.f / a, ib = 1.f / b2;
        const int rA = n0 + w * 32 + mt * 16 + g;
        float* outA = g_ao + ((size_t)(bb * NN) + rA) * CDIM + hh * DHEAD;
        float* outB = outA + (size_t)8 * CDIM;
        #pragma unroll
        for (int nt = 0; nt < 4; nt++) {
            int col = nt * 8 + t4 * 2;
            *(float2*)(outA + col) = make_float2(of[mt][nt][0] * ia, of[mt][nt][1] * ia);
            *(float2*)(outB + col) = make_float2(of[mt][nt][2] * ib, of[mt][nt][3] * ib);
        }
    }
}

// ---------------------------------------------------------------------------
// Kernel 3: projection GEMM + bias (fp32 FMA, unchanged).
// ---------------------------------------------------------------------------
__global__ __launch_bounds__(256) void proj_gemm(const float* __restrict__ w,
                                                 const float* __restrict__ bias,
                                                 float* __restrict__ out) {
    __shared__ float As[8][136];
    __shared__ float Bs[8][136];

    const int m0 = blockIdx.x * 128;
    const int o0 = blockIdx.y * 128;
    const int b  = m0 / NN;
    const int t  = threadIdx.x;

    float acc[8][8];
    #pragma unroll
    for (int i = 0; i < 8; i++)
        #pragma unroll
        for (int j = 0; j < 8; j++) acc[i][j] = 0.f;

    const int tr = (t >> 4) << 3;
    const int tc = (t & 15) << 3;

    for (int k0 = 0; k0 < CDIM; k0 += 8) {
        #pragma unroll
        for (int r = 0; r < 4; r++) {
            int i  = t + 256 * r;
            int kk = i & 7, mm = i >> 3;
            As[kk][mm] = g_ao[(size_t)(m0 + mm) * CDIM + k0 + kk];
        }
        #pragma unroll
        for (int r = 0; r < 4; r++) {
            int i  = t + 256 * r;
            int kk = i & 7, oo = i >> 3;
            Bs[kk][oo] = w[(size_t)(o0 + oo) * CDIM + k0 + kk];
        }
        __syncthreads();
        #pragma unroll
        for (int kk = 0; kk < 8; kk++) {
            float4 a0 = *(const float4*)&As[kk][tr];
            float4 a1 = *(const float4*)&As[kk][tr + 4];
            float4 b0 = *(const float4*)&Bs[kk][tc];
            float4 b1 = *(const float4*)&Bs[kk][tc + 4];
            float a[8] = {a0.x, a0.y, a0.z, a0.w, a1.x, a1.y, a1.z, a1.w};
            float bb[8] = {b0.x, b0.y, b0.z, b0.w, b1.x, b1.y, b1.z, b1.w};
            #pragma unroll
            for (int i = 0; i < 8; i++)
                #pragma unroll
                for (int j = 0; j < 8; j++) acc[i][j] += a[i] * bb[j];
        }
        __syncthreads();
    }

    #pragma unroll
    for (int i = 0; i < 8; i++) {
        int n = (m0 + tr + i) & (NN - 1);
        #pragma unroll
        for (int j = 0; j < 8; j++) {
            int c = o0 + tc + j;
            out[((size_t)b * CDIM + c) * NN + n] = acc[i][j] + bias[c];
        }
    }
}

// ---------------------------------------------------------------------------
extern "C" void kernel_launch(void* const* d_in, const int* in_sizes, int n_in,
                              void* d_out, int out_size) {
    const float* x      = (const float*)d_in[0];   // [16,384,32,32]
    const float* qkv_w  = (const float*)d_in[1];   // [1152,384]
    const float* proj_w = (const float*)d_in[2];   // [384,384]
    const float* proj_b = (const float*)d_in[3];   // [384]
    float* out = (float*)d_out;                    // [16,384,32,32]

    qkv_gemm<<<dim3(MT / 128, (3 * CDIM) / 128), 256>>>(x, qkv_w);
    attn_mma<<<dim3(NN / 128, NB * NHEAD), 128>>>();
    proj_gemm<<<dim3(MT / 128, CDIM / 128), 256>>>(proj_w, proj_b, out);
}

// round 7
// speedup vs baseline: 3.4095x; 1.9255x over previous
#include <cuda_runtime.h>
#include <cuda_bf16.h>
#include <cstdint>

// Problem constants
constexpr int CDIM  = 384;
constexpr int NHEAD = 12;
constexpr int DHEAD = 32;
constexpr int NB    = 16;
constexpr int NN    = 1024;            // 32*32 tokens
constexpr int MT    = NB * NN;         // 16384 rows
constexpr float QK_SCALE = 0.17677669529663687f; // 32^-0.5
constexpr float LOG2E    = 1.4426950408889634f;

// Scratch (static device globals; no runtime allocation)
__device__ float          g_q [(size_t)NB * NHEAD * NN * DHEAD];  // fp32 Q
__device__ __nv_bfloat16  g_kh[(size_t)NB * NHEAD * NN * DHEAD];
__device__ __nv_bfloat16  g_kl[(size_t)NB * NHEAD * NN * DHEAD];
__device__ __nv_bfloat16  g_vh[(size_t)NB * NHEAD * NN * DHEAD];
__device__ __nv_bfloat16  g_vl[(size_t)NB * NHEAD * NN * DHEAD];
__device__ __nv_bfloat16  g_xh[(size_t)MT * CDIM];   // x transposed [m][k]
__device__ __nv_bfloat16  g_xl[(size_t)MT * CDIM];
__device__ __nv_bfloat16  g_wh[(size_t)3 * CDIM * CDIM];   // qkv_w [o][k]
__device__ __nv_bfloat16  g_wl[(size_t)3 * CDIM * CDIM];
__device__ __nv_bfloat16  g_pwh[(size_t)CDIM * CDIM];      // proj_w [o][k]
__device__ __nv_bfloat16  g_pwl[(size_t)CDIM * CDIM];
__device__ __nv_bfloat16  g_aoh[(size_t)MT * CDIM];  // attention out [m][c]
__device__ __nv_bfloat16  g_aol[(size_t)MT * CDIM];

// ===========================================================================
// Helpers
// ===========================================================================
__device__ __forceinline__ float ex2f(float x) {
    float y; asm("ex2.approx.ftz.f32 %0, %1;" : "=f"(y) : "f"(x)); return y;
}
__device__ __forceinline__ void split1(float a, __nv_bfloat16& h, __nv_bfloat16& l) {
    h = __float2bfloat16(a);
    l = __float2bfloat16(a - __bfloat162float(h));
}
// Split (a,b) into bf16 hi pair and bf16 lo (residual) pair, packed b32.
__device__ __forceinline__ void split2(float a, float b, uint32_t& hi, uint32_t& lo) {
    __nv_bfloat16 ah = __float2bfloat16(a), bh = __float2bfloat16(b);
    float ar = a - __bfloat162float(ah), br = b - __bfloat162float(bh);
    __nv_bfloat162 H = __halves2bfloat162(ah, bh);
    __nv_bfloat162 L = __halves2bfloat162(__float2bfloat16(ar), __float2bfloat16(br));
    hi = *(uint32_t*)&H; lo = *(uint32_t*)&L;
}
__device__ __forceinline__ uint32_t smem_u32(const void* p) {
    uint32_t a;
    asm("{ .reg .u64 t; cvta.to.shared.u64 t, %1; cvt.u32.u64 %0, t; }"
        : "=r"(a) : "l"(p));
    return a;
}
#define LDMX2(r0, r1, addr) \
    asm volatile("ldmatrix.sync.aligned.m8n8.x2.shared.b16 {%0,%1}, [%2];" \
                 : "=r"(r0), "=r"(r1) : "r"(addr))
#define LDMX2T(r0, r1, addr) \
    asm volatile("ldmatrix.sync.aligned.m8n8.x2.trans.shared.b16 {%0,%1}, [%2];" \
                 : "=r"(r0), "=r"(r1) : "r"(addr))
#define LDMX4(r, addr) \
    asm volatile("ldmatrix.sync.aligned.m8n8.x4.shared.b16 {%0,%1,%2,%3}, [%4];" \
                 : "=r"((r)[0]), "=r"((r)[1]), "=r"((r)[2]), "=r"((r)[3]) : "r"(addr))
__device__ __forceinline__ void mma_bf16(float* d, const uint32_t* a,
                                         uint32_t b0, uint32_t b1) {
    asm volatile(
        "mma.sync.aligned.m16n8k16.row.col.f32.bf16.bf16.f32 "
        "{%0,%1,%2,%3}, {%4,%5,%6,%7}, {%8,%9}, {%0,%1,%2,%3};"
        : "+f"(d[0]), "+f"(d[1]), "+f"(d[2]), "+f"(d[3])
        : "r"(a[0]), "r"(a[1]), "r"(a[2]), "r"(a[3]), "r"(b0), "r"(b1));
}

// ---------------------------------------------------------------------------
// Kernel 0a: transpose+split x [b,c,n] fp32  ->  g_xh/g_xl [m=b*NN+n][k=c] bf16
// ---------------------------------------------------------------------------
__global__ __launch_bounds__(256) void convert_x(const float* __restrict__ x) {
    __shared__ float tile[32][33];
    const int b  = blockIdx.z;
    const int n0 = blockIdx.x * 32;
    const int c0 = blockIdx.y * 32;
    const int tx = threadIdx.x, ty = threadIdx.y;   // (32, 8)
    #pragma unroll
    for (int j = 0; j < 4; j++) {
        int c = c0 + ty + j * 8;
        tile[ty + j * 8][tx] = x[((size_t)b * CDIM + c) * NN + n0 + tx];
    }
    __syncthreads();
    #pragma unroll
    for (int j = 0; j < 4; j++) {
        int n = n0 + ty + j * 8;
        float v = tile[tx][ty + j * 8];
        __nv_bfloat16 h, l; split1(v, h, l);
        size_t idx = ((size_t)b * NN + n) * CDIM + c0 + tx;
        g_xh[idx] = h; g_xl[idx] = l;
    }
}

// ---------------------------------------------------------------------------
// Kernel 0b: split weights (qkv_w and proj_w) into bf16 hi/lo.
// ---------------------------------------------------------------------------
__global__ __launch_bounds__(256) void convert_w(const float* __restrict__ qkv_w,
                                                 const float* __restrict__ proj_w) {
    const int i = blockIdx.x * 256 + threadIdx.x;
    const int NW = 3 * CDIM * CDIM;
    if (i < NW) {
        __nv_bfloat16 h, l; split1(qkv_w[i], h, l);
        g_wh[i] = h; g_wl[i] = l;
    }
    if (i < CDIM * CDIM) {
        __nv_bfloat16 h, l; split1(proj_w[i], h, l);
        g_pwh[i] = h; g_pwl[i] = l;
    }
}

// ---------------------------------------------------------------------------
// Kernel 1: QKV GEMM on mma.sync bf16x3.
// C[m][o] = sum_k xT[m][k] * w[o][k].  Block 128m x 128o, 8 warps, k-step 32.
// Epilogue: Q -> fp32 g_q[bh][n][d];  K/V -> pre-split bf16 g_k*/g_v*.
// ---------------------------------------------------------------------------
constexpr int GROWB = 80;   // 32 bf16 = 64B data + 16B pad

__global__ __launch_bounds__(256) void qkv_mma() {
    __shared__ __align__(16) char sAh[128 * GROWB], sAl[128 * GROWB];
    __shared__ __align__(16) char sBh[128 * GROWB], sBl[128 * GROWB];

    const int tid  = threadIdx.x;
    const int w    = tid >> 5, lane = tid & 31;
    const int mw   = w & 1,   ow   = w >> 1;      // warp tile: 64m x 32o
    const int m0   = blockIdx.x * 128;
    const int o0   = blockIdx.y * 128;
    const int b    = m0 >> 10;

    const uint32_t ah_s = smem_u32(sAh), al_s = smem_u32(sAl);
    const uint32_t bh_s = smem_u32(sBh), bl_s = smem_u32(sBl);

    float acc[4][4][4];
    #pragma unroll
    for (int mt = 0; mt < 4; mt++)
        #pragma unroll
        for (int nt = 0; nt < 4; nt++)
            #pragma unroll
            for (int e = 0; e < 4; e++) acc[mt][nt][e] = 0.f;

    for (int it = 0; it < CDIM / 32; it++) {
        const int k0 = it * 32;
        __syncthreads();
        #pragma unroll
        for (int r = 0; r < 2; r++) {
            int idx = tid + 256 * r;
            int row = idx >> 2, c4 = idx & 3;
            size_t ga = (size_t)(m0 + row) * CDIM + k0 + c4 * 8;
            size_t gb = (size_t)(o0 + row) * CDIM + k0 + c4 * 8;
            *(uint4*)(sAh + row * GROWB + c4 * 16) = *(const uint4*)(g_xh + ga);
            *(uint4*)(sAl + row * GROWB + c4 * 16) = *(const uint4*)(g_xl + ga);
            *(uint4*)(sBh + row * GROWB + c4 * 16) = *(const uint4*)(g_wh + gb);
            *(uint4*)(sBl + row * GROWB + c4 * 16) = *(const uint4*)(g_wl + gb);
        }
        __syncthreads();

        #pragma unroll
        for (int ks = 0; ks < 2; ks++) {
            uint32_t ah[4][4], al[4][4];
            const uint32_t aoff = (uint32_t)((mw * 64 + (lane & 15)) * GROWB
                                             + (ks * 16 + (lane >> 4) * 8) * 2);
            #pragma unroll
            for (int mt = 0; mt < 4; mt++) {
                LDMX4(ah[mt], ah_s + aoff + mt * 16 * GROWB);
                LDMX4(al[mt], al_s + aoff + mt * 16 * GROWB);
            }
            const uint32_t boff = (uint32_t)((ow * 32 + (lane & 7)) * GROWB
                                             + (ks * 16 + ((lane >> 3) & 1) * 8) * 2);
            #pragma unroll
            for (int nt = 0; nt < 4; nt++) {
                uint32_t b0, b1, c0r, c1;
                LDMX2(b0, b1, bh_s + boff + nt * 8 * GROWB);
                LDMX2(c0r, c1, bl_s + boff + nt * 8 * GROWB);
                #pragma unroll
                for (int mt = 0; mt < 4; mt++) {
                    mma_bf16(acc[mt][nt], ah[mt], b0, b1);
                    mma_bf16(acc[mt][nt], ah[mt], c0r, c1);
                    mma_bf16(acc[mt][nt], al[mt], b0, b1);
                }
            }
        }
    }

    // Epilogue: scatter to Q (fp32) / K,V (bf16 hi+lo), layout [bh][n][d].
    const int g = lane >> 2, t4 = lane & 3;
    #pragma unroll
    for (int mt = 0; mt < 4; mt++) {
        const int n = (m0 + mw * 64 + mt * 16 + g) & (NN - 1);
        #pragma unroll
        for (int nt = 0; nt < 4; nt++) {
            const int o   = o0 + ow * 32 + nt * 8 + t4 * 2;
            const int wch = o / CDIM;
            const int rem = o % CDIM;
            const int h   = rem >> 5, d = rem & 31;
            const size_t base0 = ((size_t)(b * NHEAD + h) * NN + n) * DHEAD + d;
            const size_t base1 = base0 + 8 * DHEAD;   // row n+8
            float* ac = acc[mt][nt];
            if (wch == 0) {
                *(float2*)(g_q + base0) = make_float2(ac[0], ac[1]);
                *(float2*)(g_q + base1) = make_float2(ac[2], ac[3]);
            } else {
                __nv_bfloat16* dh = (wch == 1) ? g_kh : g_vh;
                __nv_bfloat16* dl = (wch == 1) ? g_kl : g_vl;
                uint32_t h0, l0, h1, l1;
                split2(ac[0], ac[1], h0, l0);
                split2(ac[2], ac[3], h1, l1);
                *(uint32_t*)(dh + base0) = h0; *(uint32_t*)(dl + base0) = l0;
                *(uint32_t*)(dh + base1) = h1; *(uint32_t*)(dl + base1) = l1;
            }
        }
    }
}

// ---------------------------------------------------------------------------
// Kernel 2: flash attention on mma.sync bf16x3 (K/V pre-split in gmem).
// CTA = (b,h) x 128 queries; 4 warps x 32 rows; 16 chunks of 64 keys.
// ---------------------------------------------------------------------------
constexpr int ROWB = 80;

__global__ __launch_bounds__(128) void attn_mma() {
    __shared__ __align__(16) char sk_h[64 * ROWB];
    __shared__ __align__(16) char sk_l[64 * ROWB];
    __shared__ __align__(16) char sv_h[64 * ROWB];
    __shared__ __align__(16) char sv_l[64 * ROWB];

    const int tid = threadIdx.x;
    const int w   = tid >> 5;
    const int l   = tid & 31;
    const int g   = l >> 2;
    const int t4  = l & 3;
    const int bh  = blockIdx.y;
    const int n0  = blockIdx.x * 128;

    const uint32_t skh = smem_u32(sk_h), skl = smem_u32(sk_l);
    const uint32_t svh = smem_u32(sv_h), svl = smem_u32(sv_l);

    // ---- Q fragments (scale*log2e folded), bf16 hi/lo, loaded once ----
    uint32_t qh[2][2][4], ql[2][2][4];
    {
        const float qs = QK_SCALE * LOG2E;
        const float* qb = g_q + ((size_t)bh * NN + n0 + w * 32) * DHEAD;
        #pragma unroll
        for (int mt = 0; mt < 2; mt++)
            #pragma unroll
            for (int ks = 0; ks < 2; ks++) {
                int rA = mt * 16 + g, rB = rA + 8, kk = ks * 16 + t4 * 2;
                float2 v0 = *(const float2*)(qb + rA * DHEAD + kk);
                float2 v1 = *(const float2*)(qb + rB * DHEAD + kk);
                float2 v2 = *(const float2*)(qb + rA * DHEAD + kk + 8);
                float2 v3 = *(const float2*)(qb + rB * DHEAD + kk + 8);
                split2(v0.x * qs, v0.y * qs, qh[mt][ks][0], ql[mt][ks][0]);
                split2(v1.x * qs, v1.y * qs, qh[mt][ks][1], ql[mt][ks][1]);
                split2(v2.x * qs, v2.y * qs, qh[mt][ks][2], ql[mt][ks][2]);
                split2(v3.x * qs, v3.y * qs, qh[mt][ks][3], ql[mt][ks][3]);
            }
    }

    float of[2][4][4];
    #pragma unroll
    for (int mt = 0; mt < 2; mt++)
        #pragma unroll
        for (int nt = 0; nt < 4; nt++)
            #pragma unroll
            for (int e = 0; e < 4; e++) of[mt][nt][e] = 0.f;

    float m0A[2] = {0.f, 0.f}, m0B[2] = {0.f, 0.f};
    float lA[2] = {0.f, 0.f}, lB[2] = {0.f, 0.f};

    for (int it = 0; it < 16; it++) {
        __syncthreads();
        // ---- copy pre-split K/V chunk into smem (pure uint4 moves) ----
        #pragma unroll
        for (int j = 0; j < 2; j++) {
            int idx = tid + 128 * j;
            int row = idx >> 2, c4 = idx & 3;
            size_t src = ((size_t)bh * NN + it * 64 + row) * DHEAD + c4 * 8;
            int dst = row * ROWB + c4 * 16;
            *(uint4*)(sk_h + dst) = *(const uint4*)(g_kh + src);
            *(uint4*)(sk_l + dst) = *(const uint4*)(g_kl + src);
            *(uint4*)(sv_h + dst) = *(const uint4*)(g_vh + src);
            *(uint4*)(sv_l + dst) = *(const uint4*)(g_vl + src);
        }
        __syncthreads();

        // ---- S = Q.K^T  (bf16x3) ----
        float sf[2][8][4];
        #pragma unroll
        for (int mt = 0; mt < 2; mt++)
            #pragma unroll
            for (int nt = 0; nt < 8; nt++)
                #pragma unroll
                for (int e = 0; e < 4; e++) sf[mt][nt][e] = 0.f;

        const int lane = l & 15;
        #pragma unroll
        for (int nt = 0; nt < 8; nt++) {
            #pragma unroll
            for (int ks = 0; ks < 2; ks++) {
                uint32_t aoff = (uint32_t)((nt * 8 + (lane & 7)) * ROWB
                                           + (ks * 16 + (lane >> 3) * 8) * 2);
                uint32_t bh0, bh1, bl0, bl1;
                LDMX2(bh0, bh1, skh + aoff);
                LDMX2(bl0, bl1, skl + aoff);
                #pragma unroll
                for (int mt = 0; mt < 2; mt++) {
                    mma_bf16(sf[mt][nt], qh[mt][ks], bh0, bh1);
                    mma_bf16(sf[mt][nt], qh[mt][ks], bl0, bl1);
                    mma_bf16(sf[mt][nt], ql[mt][ks], bh0, bh1);
                }
            }
        }

        // ---- softmax (log2 domain, fixed m0 from chunk 0) ----
        if (it == 0) {
            #pragma unroll
            for (int mt = 0; mt < 2; mt++) {
                float mA = -1e30f, mB = -1e30f;
                #pragma unroll
                for (int nt = 0; nt < 8; nt++) {
                    mA = fmaxf(mA, fmaxf(sf[mt][nt][0], sf[mt][nt][1]));
                    mB = fmaxf(mB, fmaxf(sf[mt][nt][2], sf[mt][nt][3]));
                }
                mA = fmaxf(mA, __shfl_xor_sync(0xffffffffu, mA, 1));
                mA = fmaxf(mA, __shfl_xor_sync(0xffffffffu, mA, 2));
                mB = fmaxf(mB, __shfl_xor_sync(0xffffffffu, mB, 1));
                mB = fmaxf(mB, __shfl_xor_sync(0xffffffffu, mB, 2));
                m0A[mt] = mA; m0B[mt] = mB;
            }
        }

        uint32_t ph[2][8][2], pl[2][8][2];
        #pragma unroll
        for (int mt = 0; mt < 2; mt++) {
            #pragma unroll
            for (int nt = 0; nt < 8; nt++) {
                float p0 = ex2f(sf[mt][nt][0] - m0A[mt]);
                float p1 = ex2f(sf[mt][nt][1] - m0A[mt]);
                float p2 = ex2f(sf[mt][nt][2] - m0B[mt]);
                float p3 = ex2f(sf[mt][nt][3] - m0B[mt]);
                lA[mt] += p0 + p1;
                lB[mt] += p2 + p3;
                split2(p0, p1, ph[mt][nt][0], pl[mt][nt][0]);
                split2(p2, p3, ph[mt][nt][1], pl[mt][nt][1]);
            }
        }

        // ---- O += P.V  (bf16x3) ----
        #pragma unroll
        for (int s = 0; s < 4; s++) {
            #pragma unroll
            for (int nt = 0; nt < 4; nt++) {
                uint32_t voff = (uint32_t)((s * 16 + lane) * ROWB + nt * 16);
                uint32_t vh0, vh1, vl0, vl1;
                LDMX2T(vh0, vh1, svh + voff);
                LDMX2T(vl0, vl1, svl + voff);
                #pragma unroll
                for (int mt = 0; mt < 2; mt++) {
                    uint32_t ah[4] = {ph[mt][2 * s][0], ph[mt][2 * s][1],
                                      ph[mt][2 * s + 1][0], ph[mt][2 * s + 1][1]};
                    uint32_t al[4] = {pl[mt][2 * s][0], pl[mt][2 * s][1],
                                      pl[mt][2 * s + 1][0], pl[mt][2 * s + 1][1]};
                    mma_bf16(of[mt][nt], ah, vh0, vh1);
                    mma_bf16(of[mt][nt], ah, vl0, vl1);
                    mma_bf16(of[mt][nt], al, vh0, vh1);
                }
            }
        }
    }

    // ---- normalize + write g_aoh/g_aol [m][c] (bf16 hi/lo for proj) ----
    const int bb = bh / NHEAD, hh = bh % NHEAD;
    #pragma unroll
    for (int mt = 0; mt < 2; mt++) {
        float a = lA[mt], b2 = lB[mt];
        a  += __shfl_xor_sync(0xffffffffu, a, 1);
        a  += __shfl_xor_sync(0xffffffffu, a, 2);
        b2 += __shfl_xor_sync(0xffffffffu, b2, 1);
        b2 += __shfl_xor_sync(0xffffffffu, b2, 2);
        const float ia = 1.f / a, ib = 1.f / b2;
        const int rA = n0 + w * 32 + mt * 16 + g;
        const size_t baseA = ((size_t)(bb * NN) + rA) * CDIM + hh * DHEAD;
        const size_t baseB = baseA + (size_t)8 * CDIM;
        #pragma unroll
        for (int nt = 0; nt < 4; nt++) {
            int col = nt * 8 + t4 * 2;
            uint32_t h0, l0, h1, l1;
            split2(of[mt][nt][0] * ia, of[mt][nt][1] * ia, h0, l0);
            split2(of[mt][nt][2] * ib, of[mt][nt][3] * ib, h1, l1);
            *(uint32_t*)(g_aoh + baseA + col) = h0;
            *(uint32_t*)(g_aol + baseA + col) = l0;
            *(uint32_t*)(g_aoh + baseB + col) = h1;
            *(uint32_t*)(g_aol + baseB + col) = l1;
        }
    }
}

// ---------------------------------------------------------------------------
// Kernel 3: projection GEMM on mma.sync bf16x3 + bias, transposed store.
// out[b,c,n] = sum_k ao[m][k] * pw[c][k] + bias[c].
// ---------------------------------------------------------------------------
__global__ __launch_bounds__(256) void proj_mma(const float* __restrict__ bias,
                                                float* __restrict__ out) {
    __shared__ __align__(16) char sAh[128 * GROWB], sAl[128 * GROWB];
    __shared__ __align__(16) char sBh[128 * GROWB], sBl[128 * GROWB];

    const int tid  = threadIdx.x;
    const int w    = tid >> 5, lane = tid & 31;
    const int mw   = w & 1,   ow   = w >> 1;
    const int m0   = blockIdx.x * 128;
    const int o0   = blockIdx.y * 128;
    const int b    = m0 >> 10;

    const uint32_t ah_s = smem_u32(sAh), al_s = smem_u32(sAl);
    const uint32_t bh_s = smem_u32(sBh), bl_s = smem_u32(sBl);

    float acc[4][4][4];
    #pragma unroll
    for (int mt = 0; mt < 4; mt++)
        #pragma unroll
        for (int nt = 0; nt < 4; nt++)
            #pragma unroll
            for (int e = 0; e < 4; e++) acc[mt][nt][e] = 0.f;

    for (int it = 0; it < CDIM / 32; it++) {
        const int k0 = it * 32;
        __syncthreads();
        #pragma unroll
        for (int r = 0; r < 2; r++) {
            int idx = tid + 256 * r;
            int row = idx >> 2, c4 = idx & 3;
            size_t ga = (size_t)(m0 + row) * CDIM + k0 + c4 * 8;
            size_t gb = (size_t)(o0 + row) * CDIM + k0 + c4 * 8;
            *(uint4*)(sAh + row * GROWB + c4 * 16) = *(const uint4*)(g_aoh + ga);
            *(uint4*)(sAl + row * GROWB + c4 * 16) = *(const uint4*)(g_aol + ga);
            *(uint4*)(sBh + row * GROWB + c4 * 16) = *(const uint4*)(g_pwh + gb);
            *(uint4*)(sBl + row * GROWB + c4 * 16) = *(const uint4*)(g_pwl + gb);
        }
        __syncthreads();

        #pragma unroll
        for (int ks = 0; ks < 2; ks++) {
            uint32_t ah[4][4], al[4][4];
            const uint32_t aoff = (uint32_t)((mw * 64 + (lane & 15)) * GROWB
                                             + (ks * 16 + (lane >> 4) * 8) * 2);
            #pragma unroll
            for (int mt = 0; mt < 4; mt++) {
                LDMX4(ah[mt], ah_s + aoff + mt * 16 * GROWB);
                LDMX4(al[mt], al_s + aoff + mt * 16 * GROWB);
            }
            const uint32_t boff = (uint32_t)((ow * 32 + (lane & 7)) * GROWB
                                             + (ks * 16 + ((lane >> 3) & 1) * 8) * 2);
            #pragma unroll
            for (int nt = 0; nt < 4; nt++) {
                uint32_t b0, b1, c0r, c1;
                LDMX2(b0, b1, bh_s + boff + nt * 8 * GROWB);
                LDMX2(c0r, c1, bl_s + boff + nt * 8 * GROWB);
                #pragma unroll
                for (int mt = 0; mt < 4; mt++) {
                    mma_bf16(acc[mt][nt], ah[mt], b0, b1);
                    mma_bf16(acc[mt][nt], ah[mt], c0r, c1);
                    mma_bf16(acc[mt][nt], al[mt], b0, b1);
                }
            }
        }
    }

    // Epilogue: out[b][o][n] = acc + bias[o]
    const int g = lane >> 2, t4 = lane & 3;
    #pragma unroll
    for (int nt = 0; nt < 4; nt++) {
        const int o = o0 + ow * 32 + nt * 8 + t4 * 2;
        const float b0v = bias[o], b1v = bias[o + 1];
        float* r0 = out + ((size_t)b * CDIM + o) * NN;
        float* r1 = r0 + NN;
        #pragma unroll
        for (int mt = 0; mt < 4; mt++) {
            const int n = (m0 + mw * 64 + mt * 16 + g) & (NN - 1);
            float* ac = acc[mt][nt];
            r0[n]     = ac[0] + b0v;
            r1[n]     = ac[1] + b1v;
            r0[n + 8] = ac[2] + b0v;
            r1[n + 8] = ac[3] + b1v;
        }
    }
}

// ---------------------------------------------------------------------------
extern "C" void kernel_launch(void* const* d_in, const int* in_sizes, int n_in,
                              void* d_out, int out_size) {
    const float* x      = (const float*)d_in[0];   // [16,384,32,32]
    const float* qkv_w  = (const float*)d_in[1];   // [1152,384]
    const float* proj_w = (const float*)d_in[2];   // [384,384]
    const float* proj_b = (const float*)d_in[3];   // [384]
    float* out = (float*)d_out;                    // [16,384,32,32]

    convert_x<<<dim3(NN / 32, CDIM / 32, NB), dim3(32, 8)>>>(x);
    convert_w<<<(3 * CDIM * CDIM + 255) / 256, 256>>>(qkv_w, proj_w);
    qkv_mma<<<dim3(MT / 128, (3 * CDIM) / 128), 256>>>();
    attn_mma<<<dim3(NN / 128, NB * NHEAD), 128>>>();
    proj_mma<<<dim3(MT / 128, CDIM / 128), 256>>>(proj_b, out);
}

// round 8
// speedup vs baseline: 3.8240x; 1.1216x over previous
#include <cuda_runtime.h>
#include <cuda_bf16.h>
#include <cstdint>

// Problem constants
constexpr int CDIM  = 384;
constexpr int NHEAD = 12;
constexpr int DHEAD = 32;
constexpr int NB    = 16;
constexpr int NN    = 1024;            // 32*32 tokens
constexpr int MT    = NB * NN;         // 16384 rows
constexpr float QK_SCALE = 0.17677669529663687f; // 32^-0.5
constexpr float LOG2E    = 1.4426950408889634f;

// Scratch (static device globals; no runtime allocation)
__device__ float          g_q [(size_t)NB * NHEAD * NN * DHEAD];  // fp32 Q
__device__ __nv_bfloat16  g_kh[(size_t)NB * NHEAD * NN * DHEAD];
__device__ __nv_bfloat16  g_kl[(size_t)NB * NHEAD * NN * DHEAD];
__device__ __nv_bfloat16  g_vh[(size_t)NB * NHEAD * NN * DHEAD];
__device__ __nv_bfloat16  g_vl[(size_t)NB * NHEAD * NN * DHEAD];
__device__ __nv_bfloat16  g_xh[(size_t)MT * CDIM];   // x transposed [m][k]
__device__ __nv_bfloat16  g_xl[(size_t)MT * CDIM];
__device__ __nv_bfloat16  g_wh[(size_t)3 * CDIM * CDIM];   // qkv_w [o][k]
__device__ __nv_bfloat16  g_wl[(size_t)3 * CDIM * CDIM];
__device__ __nv_bfloat16  g_pwh[(size_t)CDIM * CDIM];      // proj_w [o][k]
__device__ __nv_bfloat16  g_pwl[(size_t)CDIM * CDIM];
__device__ __nv_bfloat16  g_aoh[(size_t)MT * CDIM];  // attention out [m][c]
__device__ __nv_bfloat16  g_aol[(size_t)MT * CDIM];

// ===========================================================================
// Helpers
// ===========================================================================
__device__ __forceinline__ float ex2f(float x) {
    float y; asm("ex2.approx.ftz.f32 %0, %1;" : "=f"(y) : "f"(x)); return y;
}
__device__ __forceinline__ void split1(float a, __nv_bfloat16& h, __nv_bfloat16& l) {
    h = __float2bfloat16(a);
    l = __float2bfloat16(a - __bfloat162float(h));
}
// Split (a,b) into bf16 hi pair and bf16 lo (residual) pair, packed b32.
__device__ __forceinline__ void split2(float a, float b, uint32_t& hi, uint32_t& lo) {
    __nv_bfloat16 ah = __float2bfloat16(a), bh = __float2bfloat16(b);
    float ar = a - __bfloat162float(ah), br = b - __bfloat162float(bh);
    __nv_bfloat162 H = __halves2bfloat162(ah, bh);
    __nv_bfloat162 L = __halves2bfloat162(__float2bfloat16(ar), __float2bfloat16(br));
    hi = *(uint32_t*)&H; lo = *(uint32_t*)&L;
}
__device__ __forceinline__ uint32_t smem_u32(const void* p) {
    uint32_t a;
    asm("{ .reg .u64 t; cvta.to.shared.u64 t, %1; cvt.u32.u64 %0, t; }"
        : "=r"(a) : "l"(p));
    return a;
}
#define LDMX2(r0, r1, addr) \
    asm volatile("ldmatrix.sync.aligned.m8n8.x2.shared.b16 {%0,%1}, [%2];" \
                 : "=r"(r0), "=r"(r1) : "r"(addr))
#define LDMX2T(r0, r1, addr) \
    asm volatile("ldmatrix.sync.aligned.m8n8.x2.trans.shared.b16 {%0,%1}, [%2];" \
                 : "=r"(r0), "=r"(r1) : "r"(addr))
#define LDMX4(r, addr) \
    asm volatile("ldmatrix.sync.aligned.m8n8.x4.shared.b16 {%0,%1,%2,%3}, [%4];" \
                 : "=r"((r)[0]), "=r"((r)[1]), "=r"((r)[2]), "=r"((r)[3]) : "r"(addr))
__device__ __forceinline__ void mma_bf16(float* d, const uint32_t* a,
                                         uint32_t b0, uint32_t b1) {
    asm volatile(
        "mma.sync.aligned.m16n8k16.row.col.f32.bf16.bf16.f32 "
        "{%0,%1,%2,%3}, {%4,%5,%6,%7}, {%8,%9}, {%0,%1,%2,%3};"
        : "+f"(d[0]), "+f"(d[1]), "+f"(d[2]), "+f"(d[3])
        : "r"(a[0]), "r"(a[1]), "r"(a[2]), "r"(a[3]), "r"(b0), "r"(b1));
}
#define CP_ASYNC16(saddr, gptr) \
    asm volatile("cp.async.ca.shared.global [%0], [%1], 16;" \
                 :: "r"(saddr), "l"(gptr) : "memory")
#define CP_COMMIT() asm volatile("cp.async.commit_group;" ::: "memory")
#define CP_WAIT(n)  asm volatile("cp.async.wait_group %0;" :: "n"(n) : "memory")

// ---------------------------------------------------------------------------
// Kernel 0a: transpose+split x [b,c,n] fp32  ->  g_xh/g_xl [m=b*NN+n][k=c] bf16
// ---------------------------------------------------------------------------
__global__ __launch_bounds__(256) void convert_x(const float* __restrict__ x) {
    __shared__ float tile[32][33];
    const int b  = blockIdx.z;
    const int n0 = blockIdx.x * 32;
    const int c0 = blockIdx.y * 32;
    const int tx = threadIdx.x, ty = threadIdx.y;   // (32, 8)
    #pragma unroll
    for (int j = 0; j < 4; j++) {
        int c = c0 + ty + j * 8;
        tile[ty + j * 8][tx] = x[((size_t)b * CDIM + c) * NN + n0 + tx];
    }
    __syncthreads();
    #pragma unroll
    for (int j = 0; j < 4; j++) {
        int n = n0 + ty + j * 8;
        float v = tile[tx][ty + j * 8];
        __nv_bfloat16 h, l; split1(v, h, l);
        size_t idx = ((size_t)b * NN + n) * CDIM + c0 + tx;
        g_xh[idx] = h; g_xl[idx] = l;
    }
}

// ---------------------------------------------------------------------------
// Kernel 0b: split weights (qkv_w and proj_w) into bf16 hi/lo.
// ---------------------------------------------------------------------------
__global__ __launch_bounds__(256) void convert_w(const float* __restrict__ qkv_w,
                                                 const float* __restrict__ proj_w) {
    const int i = blockIdx.x * 256 + threadIdx.x;
    const int NW = 3 * CDIM * CDIM;
    if (i < NW) {
        __nv_bfloat16 h, l; split1(qkv_w[i], h, l);
        g_wh[i] = h; g_wl[i] = l;
    }
    if (i < CDIM * CDIM) {
        __nv_bfloat16 h, l; split1(proj_w[i], h, l);
        g_pwh[i] = h; g_pwl[i] = l;
    }
}

// ---------------------------------------------------------------------------
// Kernel 1: QKV GEMM on mma.sync bf16x3 (unchanged from R6, verified).
// ---------------------------------------------------------------------------
constexpr int GROWB = 80;   // 32 bf16 = 64B data + 16B pad

__global__ __launch_bounds__(256) void qkv_mma() {
    __shared__ __align__(16) char sAh[128 * GROWB], sAl[128 * GROWB];
    __shared__ __align__(16) char sBh[128 * GROWB], sBl[128 * GROWB];

    const int tid  = threadIdx.x;
    const int w    = tid >> 5, lane = tid & 31;
    const int mw   = w & 1,   ow   = w >> 1;      // warp tile: 64m x 32o
    const int m0   = blockIdx.x * 128;
    const int o0   = blockIdx.y * 128;
    const int b    = m0 >> 10;

    const uint32_t ah_s = smem_u32(sAh), al_s = smem_u32(sAl);
    const uint32_t bh_s = smem_u32(sBh), bl_s = smem_u32(sBl);

    float acc[4][4][4];
    #pragma unroll
    for (int mt = 0; mt < 4; mt++)
        #pragma unroll
        for (int nt = 0; nt < 4; nt++)
            #pragma unroll
            for (int e = 0; e < 4; e++) acc[mt][nt][e] = 0.f;

    for (int it = 0; it < CDIM / 32; it++) {
        const int k0 = it * 32;
        __syncthreads();
        #pragma unroll
        for (int r = 0; r < 2; r++) {
            int idx = tid + 256 * r;
            int row = idx >> 2, c4 = idx & 3;
            size_t ga = (size_t)(m0 + row) * CDIM + k0 + c4 * 8;
            size_t gb = (size_t)(o0 + row) * CDIM + k0 + c4 * 8;
            *(uint4*)(sAh + row * GROWB + c4 * 16) = *(const uint4*)(g_xh + ga);
            *(uint4*)(sAl + row * GROWB + c4 * 16) = *(const uint4*)(g_xl + ga);
            *(uint4*)(sBh + row * GROWB + c4 * 16) = *(const uint4*)(g_wh + gb);
            *(uint4*)(sBl + row * GROWB + c4 * 16) = *(const uint4*)(g_wl + gb);
        }
        __syncthreads();

        #pragma unroll
        for (int ks = 0; ks < 2; ks++) {
            uint32_t ah[4][4], al[4][4];
            const uint32_t aoff = (uint32_t)((mw * 64 + (lane & 15)) * GROWB
                                             + (ks * 16 + (lane >> 4) * 8) * 2);
            #pragma unroll
            for (int mt = 0; mt < 4; mt++) {
                LDMX4(ah[mt], ah_s + aoff + mt * 16 * GROWB);
                LDMX4(al[mt], al_s + aoff + mt * 16 * GROWB);
            }
            const uint32_t boff = (uint32_t)((ow * 32 + (lane & 7)) * GROWB
                                             + (ks * 16 + ((lane >> 3) & 1) * 8) * 2);
            #pragma unroll
            for (int nt = 0; nt < 4; nt++) {
                uint32_t b0, b1, c0r, c1;
                LDMX2(b0, b1, bh_s + boff + nt * 8 * GROWB);
                LDMX2(c0r, c1, bl_s + boff + nt * 8 * GROWB);
                #pragma unroll
                for (int mt = 0; mt < 4; mt++) {
                    mma_bf16(acc[mt][nt], ah[mt], b0, b1);
                    mma_bf16(acc[mt][nt], ah[mt], c0r, c1);
                    mma_bf16(acc[mt][nt], al[mt], b0, b1);
                }
            }
        }
    }

    // Epilogue: scatter to Q (fp32) / K,V (bf16 hi+lo), layout [bh][n][d].
    const int g = lane >> 2, t4 = lane & 3;
    #pragma unroll
    for (int mt = 0; mt < 4; mt++) {
        const int n = (m0 + mw * 64 + mt * 16 + g) & (NN - 1);
        #pragma unroll
        for (int nt = 0; nt < 4; nt++) {
            const int o   = o0 + ow * 32 + nt * 8 + t4 * 2;
            const int wch = o / CDIM;
            const int rem = o % CDIM;
            const int h   = rem >> 5, d = rem & 31;
            const size_t base0 = ((size_t)(b * NHEAD + h) * NN + n) * DHEAD + d;
            const size_t base1 = base0 + 8 * DHEAD;   // row n+8
            float* ac = acc[mt][nt];
            if (wch == 0) {
                *(float2*)(g_q + base0) = make_float2(ac[0], ac[1]);
                *(float2*)(g_q + base1) = make_float2(ac[2], ac[3]);
            } else {
                __nv_bfloat16* dh = (wch == 1) ? g_kh : g_vh;
                __nv_bfloat16* dl = (wch == 1) ? g_kl : g_vl;
                uint32_t h0, l0, h1, l1;
                split2(ac[0], ac[1], h0, l0);
                split2(ac[2], ac[3], h1, l1);
                *(uint32_t*)(dh + base0) = h0; *(uint32_t*)(dl + base0) = l0;
                *(uint32_t*)(dh + base1) = h1; *(uint32_t*)(dl + base1) = l1;
            }
        }
    }
}

// ---------------------------------------------------------------------------
// Kernel 2: flash attention, bf16x3 mma.sync, interleaved S/softmax/PV,
// no running max (log2-domain scores are tiny), cp.async double buffering.
// CTA = (b,h) x 128 queries; 4 warps x 32 rows; 16 chunks of 64 keys.
// ---------------------------------------------------------------------------
constexpr int ROWB = 80;

__global__ __launch_bounds__(128) void attn_mma() {
    __shared__ __align__(16) char sk_h[2][64 * ROWB];
    __shared__ __align__(16) char sk_l[2][64 * ROWB];
    __shared__ __align__(16) char sv_h[2][64 * ROWB];
    __shared__ __align__(16) char sv_l[2][64 * ROWB];

    const int tid = threadIdx.x;
    const int w   = tid >> 5;
    const int l   = tid & 31;
    const int g   = l >> 2;
    const int t4  = l & 3;
    const int bh  = blockIdx.y;
    const int n0  = blockIdx.x * 128;

    const uint32_t skh0 = smem_u32(sk_h[0]), skl0 = smem_u32(sk_l[0]);
    const uint32_t svh0 = smem_u32(sv_h[0]), svl0 = smem_u32(sv_l[0]);
    constexpr uint32_t BUFB = 64 * ROWB;

    // ---- per-thread chunk-load geometry ----
    const int    ldrow = tid >> 2, ldc4 = tid & 3;
    const size_t ldsrc0 = ((size_t)bh * NN + ldrow) * DHEAD + ldc4 * 8;
    const uint32_t lddst = (uint32_t)(ldrow * ROWB + ldc4 * 16);
    // second half: rows 32..63
    const size_t ldsrc1 = ldsrc0 + (size_t)32 * DHEAD;
    const uint32_t lddst1 = lddst + 32 * ROWB;

    // ---- Q fragments (scale*log2e folded), bf16 hi/lo, loaded once ----
    uint32_t qh[2][2][4], ql[2][2][4];
    {
        const float qs = QK_SCALE * LOG2E;
        const float* qb = g_q + ((size_t)bh * NN + n0 + w * 32) * DHEAD;
        #pragma unroll
        for (int mt = 0; mt < 2; mt++)
            #pragma unroll
            for (int ks = 0; ks < 2; ks++) {
                int rA = mt * 16 + g, rB = rA + 8, kk = ks * 16 + t4 * 2;
                float2 v0 = *(const float2*)(qb + rA * DHEAD + kk);
                float2 v1 = *(const float2*)(qb + rB * DHEAD + kk);
                float2 v2 = *(const float2*)(qb + rA * DHEAD + kk + 8);
                float2 v3 = *(const float2*)(qb + rB * DHEAD + kk + 8);
                split2(v0.x * qs, v0.y * qs, qh[mt][ks][0], ql[mt][ks][0]);
                split2(v1.x * qs, v1.y * qs, qh[mt][ks][1], ql[mt][ks][1]);
                split2(v2.x * qs, v2.y * qs, qh[mt][ks][2], ql[mt][ks][2]);
                split2(v3.x * qs, v3.y * qs, qh[mt][ks][3], ql[mt][ks][3]);
            }
    }

    float of[2][4][4];
    #pragma unroll
    for (int mt = 0; mt < 2; mt++)
        #pragma unroll
        for (int nt = 0; nt < 4; nt++)
            #pragma unroll
            for (int e = 0; e < 4; e++) of[mt][nt][e] = 0.f;

    float lA[2] = {0.f, 0.f}, lB[2] = {0.f, 0.f};

    // ---- prologue: async-load chunk 0 into buffer 0 ----
    {
        const size_t koff = 0;
        CP_ASYNC16(skh0 + lddst,  g_kh + ldsrc0 + koff);
        CP_ASYNC16(skh0 + lddst1, g_kh + ldsrc1 + koff);
        CP_ASYNC16(skl0 + lddst,  g_kl + ldsrc0 + koff);
        CP_ASYNC16(skl0 + lddst1, g_kl + ldsrc1 + koff);
        CP_ASYNC16(svh0 + lddst,  g_vh + ldsrc0 + koff);
        CP_ASYNC16(svh0 + lddst1, g_vh + ldsrc1 + koff);
        CP_ASYNC16(svl0 + lddst,  g_vl + ldsrc0 + koff);
        CP_ASYNC16(svl0 + lddst1, g_vl + ldsrc1 + koff);
        CP_COMMIT();
    }

    const int lane = l & 15;

    for (int it = 0; it < 16; it++) {
        const uint32_t bofs = (uint32_t)(it & 1) * BUFB;
        // issue next chunk into the other buffer (its last readers synced at
        // the end of iteration it-1)
        if (it < 15) {
            const uint32_t nofs = (uint32_t)((it + 1) & 1) * BUFB;
            const size_t koff = (size_t)(it + 1) * 64 * DHEAD;
            CP_ASYNC16(skh0 + nofs + lddst,  g_kh + ldsrc0 + koff);
            CP_ASYNC16(skh0 + nofs + lddst1, g_kh + ldsrc1 + koff);
            CP_ASYNC16(skl0 + nofs + lddst,  g_kl + ldsrc0 + koff);
            CP_ASYNC16(skl0 + nofs + lddst1, g_kl + ldsrc1 + koff);
            CP_ASYNC16(svh0 + nofs + lddst,  g_vh + ldsrc0 + koff);
            CP_ASYNC16(svh0 + nofs + lddst1, g_vh + ldsrc1 + koff);
            CP_ASYNC16(svl0 + nofs + lddst,  g_vl + ldsrc0 + koff);
            CP_ASYNC16(svl0 + nofs + lddst1, g_vl + ldsrc1 + koff);
            CP_COMMIT();
            CP_WAIT(1);          // chunk `it` complete (next may be in flight)
        } else {
            CP_WAIT(0);
        }
        __syncthreads();

        // ---- interleaved: per 16-key group: S-mma -> exp -> split -> PV ----
        #pragma unroll
        for (int s = 0; s < 4; s++) {
            uint32_t pfh[2][4], pfl[2][4];   // A-fragments of P for this s
            #pragma unroll
            for (int hhf = 0; hhf < 2; hhf++) {
                const int nt = 2 * s + hhf;
                float sf[2][4];
                #pragma unroll
                for (int mt = 0; mt < 2; mt++)
                    #pragma unroll
                    for (int e = 0; e < 4; e++) sf[mt][e] = 0.f;
                #pragma unroll
                for (int ks = 0; ks < 2; ks++) {
                    uint32_t aoff = bofs + (uint32_t)((nt * 8 + (lane & 7)) * ROWB
                                               + (ks * 16 + (lane >> 3) * 8) * 2);
                    uint32_t bh0, bh1, bl0, bl1;
                    LDMX2(bh0, bh1, skh0 + aoff);
                    LDMX2(bl0, bl1, skl0 + aoff);
                    #pragma unroll
                    for (int mt = 0; mt < 2; mt++) {
                        mma_bf16(sf[mt], qh[mt][ks], bh0, bh1);
                        mma_bf16(sf[mt], qh[mt][ks], bl0, bl1);
                        mma_bf16(sf[mt], ql[mt][ks], bh0, bh1);
                    }
                }
                #pragma unroll
                for (int mt = 0; mt < 2; mt++) {
                    float p0 = ex2f(sf[mt][0]);
                    float p1 = ex2f(sf[mt][1]);
                    float p2 = ex2f(sf[mt][2]);
                    float p3 = ex2f(sf[mt][3]);
                    lA[mt] += p0 + p1;
                    lB[mt] += p2 + p3;
                    split2(p0, p1, pfh[mt][hhf * 2],     pfl[mt][hhf * 2]);
                    split2(p2, p3, pfh[mt][hhf * 2 + 1], pfl[mt][hhf * 2 + 1]);
                }
            }
            // ---- O += P.V for keys [s*16, s*16+16) ----
            #pragma unroll
            for (int nt = 0; nt < 4; nt++) {
                uint32_t voff = bofs + (uint32_t)((s * 16 + lane) * ROWB + nt * 16);
                uint32_t vh0, vh1, vl0, vl1;
                LDMX2T(vh0, vh1, svh0 + voff);
                LDMX2T(vl0, vl1, svl0 + voff);
                #pragma unroll
                for (int mt = 0; mt < 2; mt++) {
                    mma_bf16(of[mt][nt], pfh[mt], vh0, vh1);
                    mma_bf16(of[mt][nt], pfh[mt], vl0, vl1);
                    mma_bf16(of[mt][nt], pfl[mt], vh0, vh1);
                }
            }
        }
        __syncthreads();
    }

    // ---- normalize + write g_aoh/g_aol [m][c] (bf16 hi/lo for proj) ----
    const int bb = bh / NHEAD, hh = bh % NHEAD;
    #pragma unroll
    for (int mt = 0; mt < 2; mt++) {
        float a = lA[mt], b2 = lB[mt];
        a  += __shfl_xor_sync(0xffffffffu, a, 1);
        a  += __shfl_xor_sync(0xffffffffu, a, 2);
        b2 += __shfl_xor_sync(0xffffffffu, b2, 1);
        b2 += __shfl_xor_sync(0xffffffffu, b2, 2);
        const float ia = 1.f / a, ib = 1.f / b2;
        const int rA = n0 + w * 32 + mt * 16 + g;
        const size_t baseA = ((size_t)(bb * NN) + rA) * CDIM + hh * DHEAD;
        const size_t baseB = baseA + (size_t)8 * CDIM;
        #pragma unroll
        for (int nt = 0; nt < 4; nt++) {
            int col = nt * 8 + t4 * 2;
            uint32_t h0, l0, h1, l1;
            split2(of[mt][nt][0] * ia, of[mt][nt][1] * ia, h0, l0);
            split2(of[mt][nt][2] * ib, of[mt][nt][3] * ib, h1, l1);
            *(uint32_t*)(g_aoh + baseA + col) = h0;
            *(uint32_t*)(g_aol + baseA + col) = l0;
            *(uint32_t*)(g_aoh + baseB + col) = h1;
            *(uint32_t*)(g_aol + baseB + col) = l1;
        }
    }
}

// ---------------------------------------------------------------------------
// Kernel 3: projection GEMM on mma.sync bf16x3 + bias (unchanged from R6).
// ---------------------------------------------------------------------------
__global__ __launch_bounds__(256) void proj_mma(const float* __restrict__ bias,
                                                float* __restrict__ out) {
    __shared__ __align__(16) char sAh[128 * GROWB], sAl[128 * GROWB];
    __shared__ __align__(16) char sBh[128 * GROWB], sBl[128 * GROWB];

    const int tid  = threadIdx.x;
    const int w    = tid >> 5, lane = tid & 31;
    const int mw   = w & 1,   ow   = w >> 1;
    const int m0   = blockIdx.x * 128;
    const int o0   = blockIdx.y * 128;
    const int b    = m0 >> 10;

    const uint32_t ah_s = smem_u32(sAh), al_s = smem_u32(sAl);
    const uint32_t bh_s = smem_u32(sBh), bl_s = smem_u32(sBl);

    float acc[4][4][4];
    #pragma unroll
    for (int mt = 0; mt < 4; mt++)
        #pragma unroll
        for (int nt = 0; nt < 4; nt++)
            #pragma unroll
            for (int e = 0; e < 4; e++) acc[mt][nt][e] = 0.f;

    for (int it = 0; it < CDIM / 32; it++) {
        const int k0 = it * 32;
        __syncthreads();
        #pragma unroll
        for (int r = 0; r < 2; r++) {
            int idx = tid + 256 * r;
            int row = idx >> 2, c4 = idx & 3;
            size_t ga = (size_t)(m0 + row) * CDIM + k0 + c4 * 8;
            size_t gb = (size_t)(o0 + row) * CDIM + k0 + c4 * 8;
            *(uint4*)(sAh + row * GROWB + c4 * 16) = *(const uint4*)(g_aoh + ga);
            *(uint4*)(sAl + row * GROWB + c4 * 16) = *(const uint4*)(g_aol + ga);
            *(uint4*)(sBh + row * GROWB + c4 * 16) = *(const uint4*)(g_pwh + gb);
            *(uint4*)(sBl + row * GROWB + c4 * 16) = *(const uint4*)(g_pwl + gb);
        }
        __syncthreads();

        #pragma unroll
        for (int ks = 0; ks < 2; ks++) {
            uint32_t ah[4][4], al[4][4];
            const uint32_t aoff = (uint32_t)((mw * 64 + (lane & 15)) * GROWB
                                             + (ks * 16 + (lane >> 4) * 8) * 2);
            #pragma unroll
            for (int mt = 0; mt < 4; mt++) {
                LDMX4(ah[mt], ah_s + aoff + mt * 16 * GROWB);
                LDMX4(al[mt], al_s + aoff + mt * 16 * GROWB);
            }
            const uint32_t boff = (uint32_t)((ow * 32 + (lane & 7)) * GROWB
                                             + (ks * 16 + ((lane >> 3) & 1) * 8) * 2);
            #pragma unroll
            for (int nt = 0; nt < 4; nt++) {
                uint32_t b0, b1, c0r, c1;
                LDMX2(b0, b1, bh_s + boff + nt * 8 * GROWB);
                LDMX2(c0r, c1, bl_s + boff + nt * 8 * GROWB);
                #pragma unroll
                for (int mt = 0; mt < 4; mt++) {
                    mma_bf16(acc[mt][nt], ah[mt], b0, b1);
                    mma_bf16(acc[mt][nt], ah[mt], c0r, c1);
                    mma_bf16(acc[mt][nt], al[mt], b0, b1);
                }
            }
        }
    }

    // Epilogue: out[b][o][n] = acc + bias[o]
    const int g = lane >> 2, t4 = lane & 3;
    #pragma unroll
    for (int nt = 0; nt < 4; nt++) {
        const int o = o0 + ow * 32 + nt * 8 + t4 * 2;
        const float b0v = bias[o], b1v = bias[o + 1];
        float* r0 = out + ((size_t)b * CDIM + o) * NN;
        float* r1 = r0 + NN;
        #pragma unroll
        for (int mt = 0; mt < 4; mt++) {
            const int n = (m0 + mw * 64 + mt * 16 + g) & (NN - 1);
            float* ac = acc[mt][nt];
            r0[n]     = ac[0] + b0v;
            r1[n]     = ac[1] + b1v;
            r0[n + 8] = ac[2] + b0v;
            r1[n + 8] = ac[3] + b1v;
        }
    }
}

// ---------------------------------------------------------------------------
extern "C" void kernel_launch(void* const* d_in, const int* in_sizes, int n_in,
                              void* d_out, int out_size) {
    const float* x      = (const float*)d_in[0];   // [16,384,32,32]
    const float* qkv_w  = (const float*)d_in[1];   // [1152,384]
    const float* proj_w = (const float*)d_in[2];   // [384,384]
    const float* proj_b = (const float*)d_in[3];   // [384]
    float* out = (float*)d_out;                    // [16,384,32,32]

    convert_x<<<dim3(NN / 32, CDIM / 32, NB), dim3(32, 8)>>>(x);
    convert_w<<<(3 * CDIM * CDIM + 255) / 256, 256>>>(qkv_w, proj_w);
    qkv_mma<<<dim3(MT / 128, (3 * CDIM) / 128), 256>>>();
    attn_mma<<<dim3(NN / 128, NB * NHEAD), 128>>>();
    proj_mma<<<dim3(MT / 128, CDIM / 128), 256>>>(proj_b, out);
}